// round 2
// baseline (speedup 1.0000x reference)
#include <cuda_runtime.h>
#include <math.h>

#define Bz 4
#define Tn 2048
#define Dm 1024
#define Hh 16
#define HD 64
#define NHALF 1024   // Tn/2

// Scratch (device globals — allocation-free per harness rules)
__device__ float g_Q[(size_t)Bz * Hh * Tn * HD];
__device__ float g_K[(size_t)Bz * Hh * Tn * HD];
__device__ float g_V[(size_t)Bz * Hh * Tn * HD];
__device__ float g_C[(size_t)Bz * Tn * Dm];

// ---------------------------------------------------------------------------
// GEMM: C = (A[MxK] @ B[KxN] + bias) * scale
// headmode=1: write to [b,h,t,d] scratch layout; headmode=0: plain [M,N]
// 128x128 tile, 256 threads, 8x8 micro-tile, k-step 8
// ---------------------------------------------------------------------------
__global__ __launch_bounds__(256)
void gemm128(const float* __restrict__ A, const float* __restrict__ Bm,
             const float* __restrict__ bias, float* __restrict__ C,
             int M, int N, int K, float scale, int headmode) {
    __shared__ float As[8][128];
    __shared__ float Bs[8][128];
    const int tid = threadIdx.x;
    const int m0 = blockIdx.y * 128, n0 = blockIdx.x * 128;
    const int ty = tid >> 4, tx = tid & 15;

    float acc[8][8];
#pragma unroll
    for (int i = 0; i < 8; i++)
#pragma unroll
        for (int j = 0; j < 8; j++) acc[i][j] = 0.0f;

    const int arow = tid >> 1, ac4 = (tid & 1) * 4;
    const int brow = tid >> 5, bc4 = (tid & 31) * 4;
    const float* Ap = A + (size_t)(m0 + arow) * K + ac4;
    const float* Bp = Bm + (size_t)brow * N + n0 + bc4;

    for (int k0 = 0; k0 < K; k0 += 8) {
        float4 a4 = *(const float4*)(Ap + k0);
        float4 b4 = *(const float4*)(Bp + (size_t)k0 * N);
        As[ac4 + 0][arow] = a4.x;
        As[ac4 + 1][arow] = a4.y;
        As[ac4 + 2][arow] = a4.z;
        As[ac4 + 3][arow] = a4.w;
        *(float4*)&Bs[brow][bc4] = b4;
        __syncthreads();
#pragma unroll
        for (int kk = 0; kk < 8; kk++) {
            float4 a0 = *(const float4*)&As[kk][ty * 8];
            float4 a1 = *(const float4*)&As[kk][ty * 8 + 4];
            float4 b0 = *(const float4*)&Bs[kk][tx * 8];
            float4 b1 = *(const float4*)&Bs[kk][tx * 8 + 4];
            float a[8] = {a0.x, a0.y, a0.z, a0.w, a1.x, a1.y, a1.z, a1.w};
            float b[8] = {b0.x, b0.y, b0.z, b0.w, b1.x, b1.y, b1.z, b1.w};
#pragma unroll
            for (int i = 0; i < 8; i++)
#pragma unroll
                for (int j = 0; j < 8; j++) acc[i][j] += a[i] * b[j];
        }
        __syncthreads();
    }

#pragma unroll
    for (int i = 0; i < 8; i++) {
        int m = m0 + ty * 8 + i;
#pragma unroll
        for (int j = 0; j < 8; j++) {
            int nn = n0 + tx * 8 + j;
            float v = (acc[i][j] + bias[nn]) * scale;
            if (headmode) {
                int bb = m / Tn, t = m - bb * Tn;
                int h = nn >> 6, dd = nn & 63;
                C[((((size_t)bb * Hh + h) * Tn + t) << 6) + dd] = v;
            } else {
                C[(size_t)m * N + nn] = v;
            }
        }
    }
}

// ---------------------------------------------------------------------------
// BD3LM mask predicate
// ---------------------------------------------------------------------------
__device__ __forceinline__ bool can_attend(int q, int kv, int bs) {
    bool x0q = q >= NHALF, x0k = kv >= NHALF;
    int bq = (x0q ? q - NHALF : q) / bs;
    int bk = (x0k ? kv - NHALF : kv) / bs;
    return (bq == bk && x0q == x0k) ||
           (bq > bk && x0k && !x0q) ||
           (bq >= bk && x0k && x0q);
}

// ---------------------------------------------------------------------------
// Fused masked flash attention: 64q x 64k tiles, tile-level skipping.
// Q already scaled by hd^-0.5. Output to ctx [B,T,D] layout.
// smem: Qs(64x65) Ks(64x65) Vs(64x64) Ps(64x65)
// ---------------------------------------------------------------------------
#define ATTN_SMEM ((64 * 65 * 3 + 64 * 64) * 4)

__global__ __launch_bounds__(256)
void attn_kernel(const float* __restrict__ Q, const float* __restrict__ K,
                 const float* __restrict__ V, float* __restrict__ C,
                 const int* __restrict__ bs_ptr) {
    extern __shared__ float sm[];
    float* Qs = sm;                 // 64*65
    float* Ks = Qs + 64 * 65;       // 64*65
    float* Vs = Ks + 64 * 65;       // 64*64
    float* Ps = Vs + 64 * 64;       // 64*65

    int bs = 4;
    if (bs_ptr) {
        int v = *bs_ptr;
        if (v >= 1 && v <= Tn) bs = v;
    }

    const int tid = threadIdx.x;
    const int qt = blockIdx.x, h = blockIdx.y, b = blockIdx.z;
    const int q0 = qt * 64;
    const size_t base = ((size_t)b * Hh + h) * Tn * HD;

    // Load Q tile (coalesced), store stride-65
    {
        int r = tid >> 2, cs = (tid & 3) * 16;
        const float* src = Q + base + (size_t)(q0 + r) * HD + cs;
#pragma unroll
        for (int i = 0; i < 4; i++) {
            float4 v4 = *(const float4*)(src + i * 4);
            Qs[r * 65 + cs + i * 4 + 0] = v4.x;
            Qs[r * 65 + cs + i * 4 + 1] = v4.y;
            Qs[r * 65 + cs + i * 4 + 2] = v4.z;
            Qs[r * 65 + cs + i * 4 + 3] = v4.w;
        }
    }

    const int ty = tid >> 4, tx = tid & 15;
    float m_i[4], l_i[4], acc[4][4];
#pragma unroll
    for (int i = 0; i < 4; i++) {
        m_i[i] = -1e30f;
        l_i[i] = 0.0f;
#pragma unroll
        for (int j = 0; j < 4; j++) acc[i][j] = 0.0f;
    }

    const bool x0q = q0 >= NHALF;
    const int bqlo = (x0q ? q0 - NHALF : q0) / bs;
    const int bqhi = (x0q ? q0 + 63 - NHALF : q0 + 63) / bs;

    for (int kt = 0; kt < Tn / 64; kt++) {
        const int k0 = kt * 64;
        // Tile-level skip (uniform across block)
        {
            bool x0k = k0 >= NHALF;
            int bklo = (x0k ? k0 - NHALF : k0) / bs;
            int bkhi = (x0k ? k0 + 63 - NHALF : k0 + 63) / bs;
            bool any = (x0q == x0k && bqhi >= bklo && bkhi >= bqlo) ||
                       (!x0q && x0k && bqhi > bklo) ||
                       (x0q && x0k && bqhi >= bklo);
            if (!any) continue;
        }
        __syncthreads();  // prior AV pass done before overwriting K/V tiles
        // Load K,V tiles
        {
            int r = tid >> 2, cs = (tid & 3) * 16;
            const float* ksrc = K + base + (size_t)(k0 + r) * HD + cs;
            const float* vsrc = V + base + (size_t)(k0 + r) * HD + cs;
#pragma unroll
            for (int i = 0; i < 4; i++) {
                float4 k4 = *(const float4*)(ksrc + i * 4);
                Ks[r * 65 + cs + i * 4 + 0] = k4.x;
                Ks[r * 65 + cs + i * 4 + 1] = k4.y;
                Ks[r * 65 + cs + i * 4 + 2] = k4.z;
                Ks[r * 65 + cs + i * 4 + 3] = k4.w;
                *(float4*)(Vs + r * 64 + cs + i * 4) = *(const float4*)(vsrc + i * 4);
            }
        }
        __syncthreads();

        // S = Q @ K^T for this tile (4x4 per thread)
        float s[4][4];
#pragma unroll
        for (int i = 0; i < 4; i++)
#pragma unroll
            for (int j = 0; j < 4; j++) s[i][j] = 0.0f;
#pragma unroll 8
        for (int d = 0; d < 64; d++) {
            float a[4], bb[4];
#pragma unroll
            for (int i = 0; i < 4; i++) a[i] = Qs[(ty * 4 + i) * 65 + d];
#pragma unroll
            for (int j = 0; j < 4; j++) bb[j] = Ks[(tx * 4 + j) * 65 + d];
#pragma unroll
            for (int i = 0; i < 4; i++)
#pragma unroll
                for (int j = 0; j < 4; j++) s[i][j] += a[i] * bb[j];
        }

        // Mask
#pragma unroll
        for (int i = 0; i < 4; i++) {
            int q = q0 + ty * 4 + i;
#pragma unroll
            for (int j = 0; j < 4; j++) {
                int kv = k0 + tx * 4 + j;
                if (!can_attend(q, kv, bs)) s[i][j] = -1e30f;
            }
        }

        // Online softmax (reduce across tx = lane bits 0..3)
#pragma unroll
        for (int i = 0; i < 4; i++) {
            float rm = fmaxf(fmaxf(s[i][0], s[i][1]), fmaxf(s[i][2], s[i][3]));
            rm = fmaxf(rm, __shfl_xor_sync(0xffffffffu, rm, 1));
            rm = fmaxf(rm, __shfl_xor_sync(0xffffffffu, rm, 2));
            rm = fmaxf(rm, __shfl_xor_sync(0xffffffffu, rm, 4));
            rm = fmaxf(rm, __shfl_xor_sync(0xffffffffu, rm, 8));
            float mnew = fmaxf(m_i[i], rm);
            float rs = 0.0f;
#pragma unroll
            for (int j = 0; j < 4; j++) {
                s[i][j] = __expf(s[i][j] - mnew);
                rs += s[i][j];
            }
            rs += __shfl_xor_sync(0xffffffffu, rs, 1);
            rs += __shfl_xor_sync(0xffffffffu, rs, 2);
            rs += __shfl_xor_sync(0xffffffffu, rs, 4);
            rs += __shfl_xor_sync(0xffffffffu, rs, 8);
            float f = __expf(m_i[i] - mnew);
            l_i[i] = l_i[i] * f + rs;
            m_i[i] = mnew;
#pragma unroll
            for (int j = 0; j < 4; j++) {
                acc[i][j] *= f;
                Ps[(ty * 4 + i) * 65 + tx * 4 + j] = s[i][j];
            }
        }
        __syncthreads();

        // O += P @ V
#pragma unroll 8
        for (int k = 0; k < 64; k++) {
            float a[4], bb[4];
#pragma unroll
            for (int i = 0; i < 4; i++) a[i] = Ps[(ty * 4 + i) * 65 + k];
#pragma unroll
            for (int j = 0; j < 4; j++) bb[j] = Vs[k * 64 + tx * 4 + j];
#pragma unroll
            for (int i = 0; i < 4; i++)
#pragma unroll
                for (int j = 0; j < 4; j++) acc[i][j] += a[i] * bb[j];
        }
    }

    // Epilogue: ctx[b][t][h*64+d]
#pragma unroll
    for (int i = 0; i < 4; i++) {
        float inv = 1.0f / l_i[i];
        int t = q0 + ty * 4 + i;
#pragma unroll
        for (int j = 0; j < 4; j++) {
            C[((size_t)b * Tn + t) * Dm + h * HD + tx * 4 + j] = acc[i][j] * inv;
        }
    }
}

// ---------------------------------------------------------------------------
extern "C" void kernel_launch(void* const* d_in, const int* in_sizes, int n_in,
                              void* d_out, int out_size) {
    const float* x  = (const float*)d_in[0];
    const float* Wq = (const float*)d_in[1];
    const float* bq = (const float*)d_in[2];
    const float* Wk = (const float*)d_in[3];
    const float* bk = (const float*)d_in[4];
    const float* Wv = (const float*)d_in[5];
    const float* bv = (const float*)d_in[6];
    const float* Wo = (const float*)d_in[7];
    const float* bo = (const float*)d_in[8];
    const int* bsp  = (n_in > 9) ? (const int*)d_in[9] : nullptr;

    float *qb, *kb, *vb, *cb;
    cudaGetSymbolAddress((void**)&qb, g_Q);
    cudaGetSymbolAddress((void**)&kb, g_K);
    cudaGetSymbolAddress((void**)&vb, g_V);
    cudaGetSymbolAddress((void**)&cb, g_C);

    cudaFuncSetAttribute(attn_kernel, cudaFuncAttributeMaxDynamicSharedMemorySize,
                         ATTN_SMEM);

    const int M = Bz * Tn;
    dim3 gg(Dm / 128, M / 128);
    const float qscale = 0.125f;  // hd^-0.5, hd=64

    gemm128<<<gg, 256>>>(x, Wq, bq, qb, M, Dm, Dm, qscale, 1);
    gemm128<<<gg, 256>>>(x, Wk, bk, kb, M, Dm, Dm, 1.0f, 1);
    gemm128<<<gg, 256>>>(x, Wv, bv, vb, M, Dm, Dm, 1.0f, 1);

    dim3 ga(Tn / 64, Hh, Bz);
    attn_kernel<<<ga, 256, ATTN_SMEM>>>(qb, kb, vb, cb, bsp);

    gemm128<<<gg, 256>>>(cb, Wo, bo, (float*)d_out, M, Dm, Dm, 1.0f, 0);
}

// round 4
// speedup vs baseline: 1.5419x; 1.5419x over previous
#include <cuda_runtime.h>
#include <math.h>
#include <stdint.h>

#define Bz 4
#define Tn 2048
#define Dm 1024
#define Hh 16
#define HD 64
#define NHALF 1024   // Tn/2

// Scratch (device globals — allocation-free per harness rules)
__device__ float g_Q[(size_t)Bz * Hh * Tn * HD];
__device__ float g_K[(size_t)Bz * Hh * Tn * HD];
__device__ float g_V[(size_t)Bz * Hh * Tn * HD];
__device__ float g_C[(size_t)Bz * Tn * Dm];

// ---------------------------------------------------------------------------
// 3xTF32 tensor-core GEMM: C = (A[MxK] @ B[KxN] + bias) * scale
// Error-compensated: x = hi + lo (both tf32); acc += hi*hi + hi*lo + lo*hi.
// 128x128 CTA tile, BK=32, 256 threads (8 warps as 2x4), warp tile 64x32.
// ---------------------------------------------------------------------------
#define ASTR 36
#define BSTR 136
#define GEMM_SMEM ((2 * 128 * ASTR + 2 * 32 * BSTR) * 4)

__device__ __forceinline__ void cp16(uint32_t dst, const void* src) {
    asm volatile("cp.async.cg.shared.global [%0], [%1], 16;\n" :: "r"(dst), "l"(src));
}
__device__ __forceinline__ void cp_commit() {
    asm volatile("cp.async.commit_group;\n");
}

__device__ __forceinline__ void mma_tf32(float c[4], uint32_t a0, uint32_t a1,
                                         uint32_t a2, uint32_t a3,
                                         uint32_t b0, uint32_t b1) {
    asm volatile(
        "mma.sync.aligned.m16n8k8.row.col.f32.tf32.tf32.f32 "
        "{%0,%1,%2,%3}, {%4,%5,%6,%7}, {%8,%9}, {%0,%1,%2,%3};\n"
        : "+f"(c[0]), "+f"(c[1]), "+f"(c[2]), "+f"(c[3])
        : "r"(a0), "r"(a1), "r"(a2), "r"(a3), "r"(b0), "r"(b1));
}

// Split float into tf32 hi + tf32 lo
__device__ __forceinline__ void tf32_split(float x, uint32_t& hi, uint32_t& lo) {
    asm("cvt.rna.tf32.f32 %0, %1;\n" : "=r"(hi) : "f"(x));
    float r = x - __uint_as_float(hi);
    asm("cvt.rna.tf32.f32 %0, %1;\n" : "=r"(lo) : "f"(r));
}

__global__ __launch_bounds__(256, 2)
void gemm_tf32x3(const float* __restrict__ A, const float* __restrict__ Bm,
                 const float* __restrict__ bias, float* __restrict__ C,
                 int M, int N, int K, float scale, int headmode) {
    extern __shared__ float sm[];
    float* Ab[2] = {sm, sm + 128 * ASTR};
    float* Bb[2] = {sm + 2 * 128 * ASTR, sm + 2 * 128 * ASTR + 32 * BSTR};

    const int tid = threadIdx.x;
    const int m0 = blockIdx.y * 128, n0 = blockIdx.x * 128;
    const int w = tid >> 5, lane = tid & 31;
    const int gid = lane >> 2, tig = lane & 3;
    const int wm = (w & 1) * 64, wn = (w >> 1) * 32;

    float acc[4][4][4];
#pragma unroll
    for (int i = 0; i < 4; i++)
#pragma unroll
        for (int j = 0; j < 4; j++)
#pragma unroll
            for (int c = 0; c < 4; c++) acc[i][j][c] = 0.0f;

    uint32_t asm_base[2], bsm_base[2];
#pragma unroll
    for (int s = 0; s < 2; s++) {
        asm_base[s] = (uint32_t)__cvta_generic_to_shared(Ab[s]);
        bsm_base[s] = (uint32_t)__cvta_generic_to_shared(Bb[s]);
    }

    auto issue_tile = [&](int k0, int s) {
#pragma unroll
        for (int i = 0; i < 4; i++) {
            int lin = tid + 256 * i;
            int row = lin >> 3, c4 = (lin & 7) * 4;
            cp16(asm_base[s] + (row * ASTR + c4) * 4,
                 A + (size_t)(m0 + row) * K + k0 + c4);
        }
#pragma unroll
        for (int i = 0; i < 4; i++) {
            int lin = tid + 256 * i;
            int row = lin >> 5, c4 = (lin & 31) * 4;
            cp16(bsm_base[s] + (row * BSTR + c4) * 4,
                 Bm + (size_t)(k0 + row) * N + n0 + c4);
        }
        cp_commit();
    };

    issue_tile(0, 0);
    int cur = 0;

    for (int k0 = 0; k0 < K; k0 += 32) {
        if (k0 + 32 < K) {
            issue_tile(k0 + 32, cur ^ 1);
            asm volatile("cp.async.wait_group 1;\n");
        } else {
            asm volatile("cp.async.wait_group 0;\n");
        }
        __syncthreads();

        const float* As = Ab[cur];
        const float* Bs = Bb[cur];
#pragma unroll
        for (int kk = 0; kk < 4; kk++) {
            const int k = kk * 8;
            uint32_t bhi[4][2], blo[4][2];
#pragma unroll
            for (int nt = 0; nt < 4; nt++) {
                float b0 = Bs[(k + tig) * BSTR + wn + nt * 8 + gid];
                float b1 = Bs[(k + tig + 4) * BSTR + wn + nt * 8 + gid];
                tf32_split(b0, bhi[nt][0], blo[nt][0]);
                tf32_split(b1, bhi[nt][1], blo[nt][1]);
            }
#pragma unroll
            for (int mt = 0; mt < 4; mt++) {
                const int r0 = (wm + mt * 16 + gid) * ASTR;
                float a0f = As[r0 + k + tig];
                float a1f = As[r0 + 8 * ASTR + k + tig];
                float a2f = As[r0 + k + tig + 4];
                float a3f = As[r0 + 8 * ASTR + k + tig + 4];
                uint32_t ah[4], al[4];
                tf32_split(a0f, ah[0], al[0]);
                tf32_split(a1f, ah[1], al[1]);
                tf32_split(a2f, ah[2], al[2]);
                tf32_split(a3f, ah[3], al[3]);
#pragma unroll
                for (int nt = 0; nt < 4; nt++) {
                    mma_tf32(acc[mt][nt], ah[0], ah[1], ah[2], ah[3],
                             bhi[nt][0], bhi[nt][1]);
                    mma_tf32(acc[mt][nt], ah[0], ah[1], ah[2], ah[3],
                             blo[nt][0], blo[nt][1]);
                    mma_tf32(acc[mt][nt], al[0], al[1], al[2], al[3],
                             bhi[nt][0], bhi[nt][1]);
                }
            }
        }
        __syncthreads();
        cur ^= 1;
    }

    // Epilogue
#pragma unroll
    for (int mt = 0; mt < 4; mt++) {
#pragma unroll
        for (int rr = 0; rr < 2; rr++) {
            int m = m0 + wm + mt * 16 + gid + rr * 8;
#pragma unroll
            for (int nt = 0; nt < 4; nt++) {
                int col = n0 + wn + nt * 8 + tig * 2;
                float v0 = (acc[mt][nt][rr * 2 + 0] + bias[col]) * scale;
                float v1 = (acc[mt][nt][rr * 2 + 1] + bias[col + 1]) * scale;
                if (headmode) {
                    int bb = m >> 11, t = m & (Tn - 1);
                    int h = col >> 6, dd = col & 63;
                    float2* dst = (float2*)&C[((((size_t)bb * Hh + h) * Tn + t) << 6) + dd];
                    *dst = make_float2(v0, v1);
                } else {
                    *(float2*)&C[(size_t)m * N + col] = make_float2(v0, v1);
                }
            }
        }
    }
}

// ---------------------------------------------------------------------------
// BD3LM mask predicate
// ---------------------------------------------------------------------------
__device__ __forceinline__ bool can_attend(int q, int kv, int bs) {
    bool x0q = q >= NHALF, x0k = kv >= NHALF;
    int bq = (x0q ? q - NHALF : q) / bs;
    int bk = (x0k ? kv - NHALF : kv) / bs;
    return (bq == bk && x0q == x0k) ||
           (bq > bk && x0k && !x0q) ||
           (bq >= bk && x0k && x0q);
}

// ---------------------------------------------------------------------------
// Fused masked flash attention: 64q x 64k tiles, tile-level skipping.
// ---------------------------------------------------------------------------
#define ATTN_SMEM ((64 * 65 * 3 + 64 * 64) * 4)

__global__ __launch_bounds__(256)
void attn_kernel(const float* __restrict__ Q, const float* __restrict__ K,
                 const float* __restrict__ V, float* __restrict__ C,
                 const int* __restrict__ bs_ptr) {
    extern __shared__ float smA[];
    float* Qs = smA;                // 64*65
    float* Ks = Qs + 64 * 65;       // 64*65
    float* Vs = Ks + 64 * 65;       // 64*64
    float* Ps = Vs + 64 * 64;       // 64*65

    int bs = 4;
    if (bs_ptr) {
        int v = *bs_ptr;
        if (v >= 1 && v <= Tn) bs = v;
    }

    const int tid = threadIdx.x;
    const int qt = blockIdx.x, h = blockIdx.y, b = blockIdx.z;
    const int q0 = qt * 64;
    const size_t base = ((size_t)b * Hh + h) * Tn * HD;

    {
        int r = tid >> 2, cs = (tid & 3) * 16;
        const float* src = Q + base + (size_t)(q0 + r) * HD + cs;
#pragma unroll
        for (int i = 0; i < 4; i++) {
            float4 v4 = *(const float4*)(src + i * 4);
            Qs[r * 65 + cs + i * 4 + 0] = v4.x;
            Qs[r * 65 + cs + i * 4 + 1] = v4.y;
            Qs[r * 65 + cs + i * 4 + 2] = v4.z;
            Qs[r * 65 + cs + i * 4 + 3] = v4.w;
        }
    }

    const int ty = tid >> 4, tx = tid & 15;
    float m_i[4], l_i[4], acc[4][4];
#pragma unroll
    for (int i = 0; i < 4; i++) {
        m_i[i] = -1e30f;
        l_i[i] = 0.0f;
#pragma unroll
        for (int j = 0; j < 4; j++) acc[i][j] = 0.0f;
    }

    const bool x0q = q0 >= NHALF;
    const int bqlo = (x0q ? q0 - NHALF : q0) / bs;
    const int bqhi = (x0q ? q0 + 63 - NHALF : q0 + 63) / bs;

    for (int kt = 0; kt < Tn / 64; kt++) {
        const int k0 = kt * 64;
        {
            bool x0k = k0 >= NHALF;
            int bklo = (x0k ? k0 - NHALF : k0) / bs;
            int bkhi = (x0k ? k0 + 63 - NHALF : k0 + 63) / bs;
            bool any = (x0q == x0k && bqhi >= bklo && bkhi >= bqlo) ||
                       (!x0q && x0k && bqhi > bklo) ||
                       (x0q && x0k && bqhi >= bklo);
            if (!any) continue;
        }
        __syncthreads();
        {
            int r = tid >> 2, cs = (tid & 3) * 16;
            const float* ksrc = K + base + (size_t)(k0 + r) * HD + cs;
            const float* vsrc = V + base + (size_t)(k0 + r) * HD + cs;
#pragma unroll
            for (int i = 0; i < 4; i++) {
                float4 k4 = *(const float4*)(ksrc + i * 4);
                Ks[r * 65 + cs + i * 4 + 0] = k4.x;
                Ks[r * 65 + cs + i * 4 + 1] = k4.y;
                Ks[r * 65 + cs + i * 4 + 2] = k4.z;
                Ks[r * 65 + cs + i * 4 + 3] = k4.w;
                *(float4*)(Vs + r * 64 + cs + i * 4) = *(const float4*)(vsrc + i * 4);
            }
        }
        __syncthreads();

        float s[4][4];
#pragma unroll
        for (int i = 0; i < 4; i++)
#pragma unroll
            for (int j = 0; j < 4; j++) s[i][j] = 0.0f;
#pragma unroll 8
        for (int d = 0; d < 64; d++) {
            float a[4], bb[4];
#pragma unroll
            for (int i = 0; i < 4; i++) a[i] = Qs[(ty * 4 + i) * 65 + d];
#pragma unroll
            for (int j = 0; j < 4; j++) bb[j] = Ks[(tx * 4 + j) * 65 + d];
#pragma unroll
            for (int i = 0; i < 4; i++)
#pragma unroll
                for (int j = 0; j < 4; j++) s[i][j] += a[i] * bb[j];
        }

#pragma unroll
        for (int i = 0; i < 4; i++) {
            int q = q0 + ty * 4 + i;
#pragma unroll
            for (int j = 0; j < 4; j++) {
                int kv = k0 + tx * 4 + j;
                if (!can_attend(q, kv, bs)) s[i][j] = -1e30f;
            }
        }

#pragma unroll
        for (int i = 0; i < 4; i++) {
            float rm = fmaxf(fmaxf(s[i][0], s[i][1]), fmaxf(s[i][2], s[i][3]));
            rm = fmaxf(rm, __shfl_xor_sync(0xffffffffu, rm, 1));
            rm = fmaxf(rm, __shfl_xor_sync(0xffffffffu, rm, 2));
            rm = fmaxf(rm, __shfl_xor_sync(0xffffffffu, rm, 4));
            rm = fmaxf(rm, __shfl_xor_sync(0xffffffffu, rm, 8));
            float mnew = fmaxf(m_i[i], rm);
            float rs = 0.0f;
#pragma unroll
            for (int j = 0; j < 4; j++) {
                s[i][j] = __expf(s[i][j] - mnew);
                rs += s[i][j];
            }
            rs += __shfl_xor_sync(0xffffffffu, rs, 1);
            rs += __shfl_xor_sync(0xffffffffu, rs, 2);
            rs += __shfl_xor_sync(0xffffffffu, rs, 4);
            rs += __shfl_xor_sync(0xffffffffu, rs, 8);
            float f = __expf(m_i[i] - mnew);
            l_i[i] = l_i[i] * f + rs;
            m_i[i] = mnew;
#pragma unroll
            for (int j = 0; j < 4; j++) {
                acc[i][j] *= f;
                Ps[(ty * 4 + i) * 65 + tx * 4 + j] = s[i][j];
            }
        }
        __syncthreads();

#pragma unroll 8
        for (int k = 0; k < 64; k++) {
            float a[4], bb[4];
#pragma unroll
            for (int i = 0; i < 4; i++) a[i] = Ps[(ty * 4 + i) * 65 + k];
#pragma unroll
            for (int j = 0; j < 4; j++) bb[j] = Vs[k * 64 + tx * 4 + j];
#pragma unroll
            for (int i = 0; i < 4; i++)
#pragma unroll
                for (int j = 0; j < 4; j++) acc[i][j] += a[i] * bb[j];
        }
    }

#pragma unroll
    for (int i = 0; i < 4; i++) {
        float inv = 1.0f / l_i[i];
        int t = q0 + ty * 4 + i;
#pragma unroll
        for (int j = 0; j < 4; j++) {
            C[((size_t)b * Tn + t) * Dm + h * HD + tx * 4 + j] = acc[i][j] * inv;
        }
    }
}

// ---------------------------------------------------------------------------
extern "C" void kernel_launch(void* const* d_in, const int* in_sizes, int n_in,
                              void* d_out, int out_size) {
    const float* x  = (const float*)d_in[0];
    const float* Wq = (const float*)d_in[1];
    const float* bq = (const float*)d_in[2];
    const float* Wk = (const float*)d_in[3];
    const float* bk = (const float*)d_in[4];
    const float* Wv = (const float*)d_in[5];
    const float* bv = (const float*)d_in[6];
    const float* Wo = (const float*)d_in[7];
    const float* bo = (const float*)d_in[8];
    const int* bsp  = (n_in > 9) ? (const int*)d_in[9] : nullptr;

    float *qb, *kb, *vb, *cb;
    cudaGetSymbolAddress((void**)&qb, g_Q);
    cudaGetSymbolAddress((void**)&kb, g_K);
    cudaGetSymbolAddress((void**)&vb, g_V);
    cudaGetSymbolAddress((void**)&cb, g_C);

    cudaFuncSetAttribute(attn_kernel, cudaFuncAttributeMaxDynamicSharedMemorySize,
                         ATTN_SMEM);
    cudaFuncSetAttribute(gemm_tf32x3, cudaFuncAttributeMaxDynamicSharedMemorySize,
                         GEMM_SMEM);

    const int M = Bz * Tn;
    dim3 gg(Dm / 128, M / 128);
    const float qscale = 0.125f;  // hd^-0.5, hd=64

    gemm_tf32x3<<<gg, 256, GEMM_SMEM>>>(x, Wq, bq, qb, M, Dm, Dm, qscale, 1);
    gemm_tf32x3<<<gg, 256, GEMM_SMEM>>>(x, Wk, bk, kb, M, Dm, Dm, 1.0f, 1);
    gemm_tf32x3<<<gg, 256, GEMM_SMEM>>>(x, Wv, bv, vb, M, Dm, Dm, 1.0f, 1);

    dim3 ga(Tn / 64, Hh, Bz);
    attn_kernel<<<ga, 256, ATTN_SMEM>>>(qb, kb, vb, cb, bsp);

    gemm_tf32x3<<<gg, 256, GEMM_SMEM>>>(cb, Wo, bo, (float*)d_out, M, Dm, Dm, 1.0f, 0);
}